// round 1
// baseline (speedup 1.0000x reference)
#include <cuda_runtime.h>

// Problem constants (fixed by the reference)
#define BATCH   1024
#define IN_DIM  2048
#define RDIM    2048          // R_IN == R_OUT
#define HIDDEN  4096

// Tile config: 128x128 output tile, BK=8, 256 threads, 8x8 per-thread microtile
#define BM 128
#define BN 128
#define BK 8
#define TM 8
#define TN 8

__global__ __launch_bounds__(256, 2)
void snn_fused_kernel(const float* __restrict__ x_t,
                      const float* __restrict__ mem_t,
                      const float* __restrict__ spk_t,
                      const float* __restrict__ b_t,
                      const float* __restrict__ W_x2in,   const float* __restrict__ b_x2in,
                      const float* __restrict__ W_rec4in, const float* __restrict__ b_rec4in,
                      const float* __restrict__ W_in2out, const float* __restrict__ b_in2out,
                      const float* __restrict__ W_rec4out,const float* __restrict__ b_rec4out,
                      const float* __restrict__ W_out2in, const float* __restrict__ b_out2in,
                      const float* __restrict__ tau_adp,  const float* __restrict__ tau_m,
                      float* __restrict__ out)
{
    __shared__ float As[BK][BM];
    __shared__ float Ws[BK][BN];

    const int n_tile = blockIdx.x * BN;   // global column in [0, HIDDEN)
    const int m_tile = blockIdx.y * BM;   // global row in [0, BATCH)
    const int tid = threadIdx.x;
    const int tx  = tid % 16;             // micro-tile column group
    const int ty  = tid / 16;             // micro-tile row group

    const bool out_half = (n_tile < RDIM);
    const int  jbase    = out_half ? n_tile : (n_tile - RDIM); // column within half

    // GEMM source list: A operand (with row stride) and weight matrix.
    // r_out (cols 0..2047):  spk_out @ W_rec4out^T + spk_in @ W_in2out^T
    // r_in  (cols 2048..):   x_t @ W_x2in^T + spk_in @ W_rec4in^T + spk_out @ W_out2in^T
    const float* Asrc[3];
    const float* Wsrc[3];
    int lda[3];
    int nsrc;
    if (out_half) {
        nsrc = 2;
        Asrc[0] = spk_t;        lda[0] = HIDDEN; Wsrc[0] = W_rec4out; // spk_out
        Asrc[1] = spk_t + RDIM; lda[1] = HIDDEN; Wsrc[1] = W_in2out;  // spk_in
    } else {
        nsrc = 3;
        Asrc[0] = x_t;          lda[0] = IN_DIM; Wsrc[0] = W_x2in;
        Asrc[1] = spk_t + RDIM; lda[1] = HIDDEN; Wsrc[1] = W_rec4in;  // spk_in
        Asrc[2] = spk_t;        lda[2] = HIDDEN; Wsrc[2] = W_out2in;  // spk_out
    }

    float acc[TM][TN];
    #pragma unroll
    for (int i = 0; i < TM; ++i)
        #pragma unroll
        for (int j = 0; j < TN; ++j)
            acc[i][j] = 0.0f;

    // smem load assignment: 256 threads load a 128x8 tile as float4
    const int lrow  = tid >> 1;        // 0..127
    const int lcol4 = (tid & 1) * 4;   // 0 or 4

    for (int s = 0; s < nsrc; ++s) {
        const float* Arow = Asrc[s] + (long)(m_tile + lrow) * lda[s];
        const float* Wrow = Wsrc[s] + (long)(jbase + lrow) * 2048;  // all weight K-strides = 2048

        for (int k0 = 0; k0 < 2048; k0 += BK) {
            const float4 av = *reinterpret_cast<const float4*>(Arow + k0 + lcol4);
            const float4 wv = *reinterpret_cast<const float4*>(Wrow + k0 + lcol4);
            As[lcol4 + 0][lrow] = av.x;
            As[lcol4 + 1][lrow] = av.y;
            As[lcol4 + 2][lrow] = av.z;
            As[lcol4 + 3][lrow] = av.w;
            Ws[lcol4 + 0][lrow] = wv.x;
            Ws[lcol4 + 1][lrow] = wv.y;
            Ws[lcol4 + 2][lrow] = wv.z;
            Ws[lcol4 + 3][lrow] = wv.w;
            __syncthreads();

            #pragma unroll
            for (int k = 0; k < BK; ++k) {
                float a[TM], w[TN];
                #pragma unroll
                for (int i = 0; i < TM; ++i) a[i] = As[k][ty * TM + i];
                #pragma unroll
                for (int j = 0; j < TN; ++j) w[j] = Ws[k][tx * TN + j];
                #pragma unroll
                for (int i = 0; i < TM; ++i)
                    #pragma unroll
                    for (int j = 0; j < TN; ++j)
                        acc[i][j] = fmaf(a[i], w[j], acc[i][j]);
            }
            __syncthreads();
        }
    }

    // ---- Epilogue: per-column constants ----
    float bias[TN], tms[TN], tas[TN];
    #pragma unroll
    for (int j = 0; j < TN; ++j) {
        const int n  = n_tile + tx * TN + j;
        if (out_half) {
            bias[j] = b_rec4out[n] + b_in2out[n];
        } else {
            const int jn = n - RDIM;
            bias[j] = b_x2in[jn] + b_rec4in[jn] + b_out2in[jn];
        }
        tms[j] = 1.0f / (1.0f + __expf(-tau_m[n]));
        tas[j] = 1.0f / (1.0f + __expf(-tau_adp[n]));
    }

    const long plane = (long)BATCH * HIDDEN;
    #pragma unroll
    for (int i = 0; i < TM; ++i) {
        const int m = m_tile + ty * TM + i;
        const long rowoff = (long)m * HIDDEN;
        #pragma unroll
        for (int j = 0; j < TN; ++j) {
            const int n = n_tile + tx * TN + j;
            const long idx = rowoff + n;

            const float inp  = acc[i][j] + bias[j];
            const float spk  = spk_t[idx];
            const float bb   = tas[j] * b_t[idx] + (1.0f - tas[j]) * spk;
            const float thre = 0.1f + 1.8f * bb;
            const float mem  = mem_t[idx] * tms[j]
                             + (1.0f - tms[j]) * 3.0f * inp
                             - thre * spk;
            const float spike = (mem - thre) > 0.0f ? 1.0f : 0.0f;

            out[idx]             = mem;
            out[plane + idx]     = spike;
            out[2 * plane + idx] = bb;
        }
    }
}

extern "C" void kernel_launch(void* const* d_in, const int* in_sizes, int n_in,
                              void* d_out, int out_size)
{
    const float* x_t       = (const float*)d_in[0];
    const float* mem_t     = (const float*)d_in[1];
    const float* spk_t     = (const float*)d_in[2];
    const float* b_t       = (const float*)d_in[3];
    const float* W_x2in    = (const float*)d_in[4];
    const float* b_x2in    = (const float*)d_in[5];
    const float* W_rec4in  = (const float*)d_in[6];
    const float* b_rec4in  = (const float*)d_in[7];
    const float* W_in2out  = (const float*)d_in[8];
    const float* b_in2out  = (const float*)d_in[9];
    const float* W_rec4out = (const float*)d_in[10];
    const float* b_rec4out = (const float*)d_in[11];
    const float* W_out2in  = (const float*)d_in[12];
    const float* b_out2in  = (const float*)d_in[13];
    const float* tau_adp   = (const float*)d_in[14];
    const float* tau_m     = (const float*)d_in[15];
    float* out = (float*)d_out;

    dim3 grid(HIDDEN / BN, BATCH / BM);   // (32, 8) = 256 CTAs
    dim3 block(256);
    snn_fused_kernel<<<grid, block>>>(x_t, mem_t, spk_t, b_t,
                                      W_x2in, b_x2in, W_rec4in, b_rec4in,
                                      W_in2out, b_in2out, W_rec4out, b_rec4out,
                                      W_out2in, b_out2in, tau_adp, tau_m, out);
}

// round 2
// speedup vs baseline: 1.0002x; 1.0002x over previous
#include <cuda_runtime.h>

// Problem constants (fixed by the reference)
#define BATCH   1024
#define IN_DIM  2048
#define RDIM    2048          // R_IN == R_OUT
#define HIDDEN  4096

// Tile config: 128x128 output tile, BK=8, 256 threads, 8x8 per-thread microtile
#define BM 128
#define BN 128
#define BK 8
#define TM 8
#define TN 8

__global__ __launch_bounds__(256, 2)
void snn_fused_kernel(const float* __restrict__ x_t,
                      const float* __restrict__ mem_t,
                      const float* __restrict__ spk_t,
                      const float* __restrict__ b_t,
                      const float* __restrict__ W_x2in,   const float* __restrict__ b_x2in,
                      const float* __restrict__ W_rec4in, const float* __restrict__ b_rec4in,
                      const float* __restrict__ W_in2out, const float* __restrict__ b_in2out,
                      const float* __restrict__ W_rec4out,const float* __restrict__ b_rec4out,
                      const float* __restrict__ W_out2in, const float* __restrict__ b_out2in,
                      const float* __restrict__ tau_adp,  const float* __restrict__ tau_m,
                      float* __restrict__ out)
{
    __shared__ float As[BK][BM];
    __shared__ float Ws[BK][BN];

    const int n_tile = blockIdx.x * BN;   // global column in [0, HIDDEN)
    const int m_tile = blockIdx.y * BM;   // global row in [0, BATCH)
    const int tid = threadIdx.x;
    const int tx  = tid % 16;             // micro-tile column group
    const int ty  = tid / 16;             // micro-tile row group

    const bool out_half = (n_tile < RDIM);
    const int  jbase    = out_half ? n_tile : (n_tile - RDIM); // column within half

    // GEMM source list: A operand (with row stride) and weight matrix.
    // r_out (cols 0..2047):  spk_out @ W_rec4out^T + spk_in @ W_in2out^T
    // r_in  (cols 2048..):   x_t @ W_x2in^T + spk_in @ W_rec4in^T + spk_out @ W_out2in^T
    const float* Asrc[3];
    const float* Wsrc[3];
    int lda[3];
    int nsrc;
    if (out_half) {
        nsrc = 2;
        Asrc[0] = spk_t;        lda[0] = HIDDEN; Wsrc[0] = W_rec4out; // spk_out
        Asrc[1] = spk_t + RDIM; lda[1] = HIDDEN; Wsrc[1] = W_in2out;  // spk_in
    } else {
        nsrc = 3;
        Asrc[0] = x_t;          lda[0] = IN_DIM; Wsrc[0] = W_x2in;
        Asrc[1] = spk_t + RDIM; lda[1] = HIDDEN; Wsrc[1] = W_rec4in;  // spk_in
        Asrc[2] = spk_t;        lda[2] = HIDDEN; Wsrc[2] = W_out2in;  // spk_out
    }

    float acc[TM][TN];
    #pragma unroll
    for (int i = 0; i < TM; ++i)
        #pragma unroll
        for (int j = 0; j < TN; ++j)
            acc[i][j] = 0.0f;

    // smem load assignment: 256 threads load a 128x8 tile as float4
    const int lrow  = tid >> 1;        // 0..127
    const int lcol4 = (tid & 1) * 4;   // 0 or 4

    for (int s = 0; s < nsrc; ++s) {
        const float* Arow = Asrc[s] + (long)(m_tile + lrow) * lda[s];
        const float* Wrow = Wsrc[s] + (long)(jbase + lrow) * 2048;  // all weight K-strides = 2048

        for (int k0 = 0; k0 < 2048; k0 += BK) {
            const float4 av = *reinterpret_cast<const float4*>(Arow + k0 + lcol4);
            const float4 wv = *reinterpret_cast<const float4*>(Wrow + k0 + lcol4);
            As[lcol4 + 0][lrow] = av.x;
            As[lcol4 + 1][lrow] = av.y;
            As[lcol4 + 2][lrow] = av.z;
            As[lcol4 + 3][lrow] = av.w;
            Ws[lcol4 + 0][lrow] = wv.x;
            Ws[lcol4 + 1][lrow] = wv.y;
            Ws[lcol4 + 2][lrow] = wv.z;
            Ws[lcol4 + 3][lrow] = wv.w;
            __syncthreads();

            #pragma unroll
            for (int k = 0; k < BK; ++k) {
                float a[TM], w[TN];
                #pragma unroll
                for (int i = 0; i < TM; ++i) a[i] = As[k][ty * TM + i];
                #pragma unroll
                for (int j = 0; j < TN; ++j) w[j] = Ws[k][tx * TN + j];
                #pragma unroll
                for (int i = 0; i < TM; ++i)
                    #pragma unroll
                    for (int j = 0; j < TN; ++j)
                        acc[i][j] = fmaf(a[i], w[j], acc[i][j]);
            }
            __syncthreads();
        }
    }

    // ---- Epilogue: per-column constants ----
    float bias[TN], tms[TN], tas[TN];
    #pragma unroll
    for (int j = 0; j < TN; ++j) {
        const int n  = n_tile + tx * TN + j;
        if (out_half) {
            bias[j] = b_rec4out[n] + b_in2out[n];
        } else {
            const int jn = n - RDIM;
            bias[j] = b_x2in[jn] + b_rec4in[jn] + b_out2in[jn];
        }
        tms[j] = 1.0f / (1.0f + __expf(-tau_m[n]));
        tas[j] = 1.0f / (1.0f + __expf(-tau_adp[n]));
    }

    const long plane = (long)BATCH * HIDDEN;
    #pragma unroll
    for (int i = 0; i < TM; ++i) {
        const int m = m_tile + ty * TM + i;
        const long rowoff = (long)m * HIDDEN;
        #pragma unroll
        for (int j = 0; j < TN; ++j) {
            const int n = n_tile + tx * TN + j;
            const long idx = rowoff + n;

            const float inp  = acc[i][j] + bias[j];
            const float spk  = spk_t[idx];
            const float bb   = tas[j] * b_t[idx] + (1.0f - tas[j]) * spk;
            const float thre = 0.1f + 1.8f * bb;
            const float mem  = mem_t[idx] * tms[j]
                             + (1.0f - tms[j]) * 3.0f * inp
                             - thre * spk;
            const float spike = (mem - thre) > 0.0f ? 1.0f : 0.0f;

            out[idx]             = mem;
            out[plane + idx]     = spike;
            out[2 * plane + idx] = bb;
        }
    }
}

extern "C" void kernel_launch(void* const* d_in, const int* in_sizes, int n_in,
                              void* d_out, int out_size)
{
    const float* x_t       = (const float*)d_in[0];
    const float* mem_t     = (const float*)d_in[1];
    const float* spk_t     = (const float*)d_in[2];
    const float* b_t       = (const float*)d_in[3];
    const float* W_x2in    = (const float*)d_in[4];
    const float* b_x2in    = (const float*)d_in[5];
    const float* W_rec4in  = (const float*)d_in[6];
    const float* b_rec4in  = (const float*)d_in[7];
    const float* W_in2out  = (const float*)d_in[8];
    const float* b_in2out  = (const float*)d_in[9];
    const float* W_rec4out = (const float*)d_in[10];
    const float* b_rec4out = (const float*)d_in[11];
    const float* W_out2in  = (const float*)d_in[12];
    const float* b_out2in  = (const float*)d_in[13];
    const float* tau_adp   = (const float*)d_in[14];
    const float* tau_m     = (const float*)d_in[15];
    float* out = (float*)d_out;

    dim3 grid(HIDDEN / BN, BATCH / BM);   // (32, 8) = 256 CTAs
    dim3 block(256);
    snn_fused_kernel<<<grid, block>>>(x_t, mem_t, spk_t, b_t,
                                      W_x2in, b_x2in, W_rec4in, b_rec4in,
                                      W_in2out, b_in2out, W_rec4out, b_rec4out,
                                      W_out2in, b_out2in, tau_adp, tau_m, out);
}